// round 7
// baseline (speedup 1.0000x reference)
#include <cuda_runtime.h>
#include <cuda_fp16.h>
#include <cstdint>
#include <cstddef>

// ============================================================================
// Quantized FFN via fp16-split warp-level mma.sync (HMMA) GEMMs.
//   GEMM1: h = q8(gelu_pwl(q8(x@w1+b1)))  -> h exact on q8 grid, stored fp16
//   GEMM2: out = q8(h@w2+b2)
// Split: hi=fp16(x), lo=fp16((x-hi)*2048).
// Main term:  tacc = Ahi*Bhi + 0 (per-MMA), master += tacc via RN FADD
//             (kills tensor-core RZ accumulation bias).
// Cross term: Dc += Ahi*Blo [+ Alo*Bhi] (plain MMA acc; error/2048 negligible).
// result = master + Dc/2048 + bias.
// R7: 512 threads, 16 warps @ 32x32 warp tile -> 64 acc regs/thread, no spill.
// ============================================================================

#define M_ROWS 16384
#define D_DIM  1024
#define F_DIM  4096

#define BM 128
#define BN 128
#define BK 64
#define NTHREADS 512

// ---------------- device scratch ----------------
__device__ __half g_a1hi [(size_t)M_ROWS * D_DIM];
__device__ __half g_a1lo [(size_t)M_ROWS * D_DIM];
__device__ __half g_w1thi[(size_t)F_DIM * D_DIM];
__device__ __half g_w1tlo[(size_t)F_DIM * D_DIM];
__device__ __half g_hbuf [(size_t)M_ROWS * F_DIM];
__device__ __half g_w2thi[(size_t)D_DIM * F_DIM];
__device__ __half g_w2tlo[(size_t)D_DIM * F_DIM];

__device__ float d_pwl_y[33] = {
    -1.2668497e-04f, -3.3156488e-04f, -8.1420185e-04f, -1.8753475e-03f,
    -4.0496940e-03f, -8.1943491e-03f, -1.5524163e-02f, -2.7505064e-02f,
    -4.5500264e-02f, -7.0103525e-02f, -1.0021080e-01f, -1.3206222e-01f,
    -1.5865525e-01f, -1.6997051e-01f, -1.5426877e-01f, -1.0032342e-01f,
     0.0000000e+00f,  1.4967658e-01f,  3.4573123e-01f,  5.8002949e-01f,
     8.4134475e-01f,  1.1179378e+00f,  1.3997892e+00f,  1.6798965e+00f,
     1.9544997e+00f,  2.2224949e+00f,  2.4844758e+00f,  2.7418056e+00f,
     2.9959503e+00f,  3.2481247e+00f,  3.4991858e+00f,  3.7496684e+00f,
     3.9998733e+00f
};

// ---------------- asm helpers ----------------
__device__ __forceinline__ uint32_t smem_u32(const void* p) {
    uint32_t a;
    asm("{ .reg .u64 t; cvta.to.shared.u64 t, %1; cvt.u32.u64 %0, t; }" : "=r"(a) : "l"(p));
    return a;
}
#define CP16(smem, gmem) \
    asm volatile("cp.async.cg.shared.global [%0], [%1], 16;" :: "r"(smem), "l"(gmem))
#define CP_COMMIT() asm volatile("cp.async.commit_group;" ::: "memory")
template<int N>
__device__ __forceinline__ void cp_wait() {
    asm volatile("cp.async.wait_group %0;" :: "n"(N) : "memory");
}

__device__ __forceinline__ void ldsm4(uint32_t* r, uint32_t addr) {
    asm volatile("ldmatrix.sync.aligned.m8n8.x4.shared.b16 {%0,%1,%2,%3}, [%4];"
        : "=r"(r[0]), "=r"(r[1]), "=r"(r[2]), "=r"(r[3]) : "r"(addr));
}
// c += a*b  (in-place accumulate)
__device__ __forceinline__ void mma16816(float* c, const uint32_t* a, uint32_t b0, uint32_t b1) {
    asm volatile("mma.sync.aligned.m16n8k16.row.col.f32.f16.f16.f32 "
        "{%0,%1,%2,%3},{%4,%5,%6,%7},{%8,%9},{%0,%1,%2,%3};"
        : "+f"(c[0]), "+f"(c[1]), "+f"(c[2]), "+f"(c[3])
        : "r"(a[0]), "r"(a[1]), "r"(a[2]), "r"(a[3]), "r"(b0), "r"(b1));
}
// d = a*b + 0  (fresh fragment; caller FADDs into master with RN)
__device__ __forceinline__ void mma16816_z(float* d, const uint32_t* a, uint32_t b0, uint32_t b1) {
    asm volatile("mma.sync.aligned.m16n8k16.row.col.f32.f16.f16.f32 "
        "{%0,%1,%2,%3},{%4,%5,%6,%7},{%8,%9},{%10,%10,%10,%10};"
        : "=f"(d[0]), "=f"(d[1]), "=f"(d[2]), "=f"(d[3])
        : "r"(a[0]), "r"(a[1]), "r"(a[2]), "r"(a[3]), "r"(b0), "r"(b1), "f"(0.0f));
}
#define SWZ(o) ((o) ^ (((o) >> 3) & 0x70))

__device__ __forceinline__ float q8(float v) { return rintf(v * 256.0f) * 0.00390625f; }

__device__ __forceinline__ float gelu_pwl(float v, const float* Ys) {
    if (v > 4.0f) return v;
    if (v < -4.0f) return 0.0f;
    float u = (v + 4.0f) * 4.0f;      // exact on q8 grid
    int idx = (int)u; if (idx > 31) idx = 31;
    float f = u - (float)idx;
    float y0 = Ys[idx], y1 = Ys[idx + 1];
    return fmaf(f, y1 - y0, y0);
}

// ---------------- prepass ----------------
__device__ __forceinline__ void split1(float x, __half& h, __half& l) {
    h = __float2half_rn(x);
    l = __float2half_rn((x - __half2float(h)) * 2048.0f);
}
__global__ void split_x_kernel(const float4* __restrict__ in, __half* __restrict__ hi,
                               __half* __restrict__ lo, int n4) {
    int i = blockIdx.x * blockDim.x + threadIdx.x;
    if (i >= n4) return;
    float4 v = in[i];
    __half h[4], l[4];
    split1(v.x, h[0], l[0]); split1(v.y, h[1], l[1]);
    split1(v.z, h[2], l[2]); split1(v.w, h[3], l[3]);
    *(uint2*)(hi + (size_t)i * 4) = *(uint2*)h;
    *(uint2*)(lo + (size_t)i * 4) = *(uint2*)l;
}
// in: [R, C] f32 -> hi/lo: [C, R] fp16 (transpose + split)
__global__ void transpose_split_kernel(const float* __restrict__ in, __half* __restrict__ hi,
                                       __half* __restrict__ lo, int R, int C) {
    __shared__ float t[32][33];
    int c0 = blockIdx.x * 32, r0 = blockIdx.y * 32;
    int tx = threadIdx.x, ty = threadIdx.y;   // 32 x 8
    #pragma unroll
    for (int i = 0; i < 32; i += 8)
        t[ty + i][tx] = in[(size_t)(r0 + ty + i) * C + c0 + tx];
    __syncthreads();
    #pragma unroll
    for (int i = 0; i < 32; i += 8) {
        __half h, l; split1(t[tx][ty + i], h, l);
        size_t o = (size_t)(c0 + ty + i) * R + r0 + tx;
        hi[o] = h; lo[o] = l;
    }
}

// ---------------- main GEMM ----------------
// C[M,N] = A[M,K] @ B[N,K]^T (+bias, q8, optional PWL-GELU)
// 16 warps in 4x4 grid, warp tile 32x32.
// Stage layout: Ahi[16K] [Alo 16K if HAS_ALO] Bhi[16K] Blo[16K]
template<bool HAS_ALO, bool GELU, int NST>
__global__ void __launch_bounds__(NTHREADS, 1)
gemm_mma(const __half* __restrict__ A, const __half* __restrict__ Alo,
         const __half* __restrict__ B, const __half* __restrict__ Blo,
         const float* __restrict__ bias,
         __half* __restrict__ outH, float* __restrict__ outF,
         int K, int N)
{
    constexpr int OFF_ALO = 16384;
    constexpr int OFF_BHI = HAS_ALO ? 32768 : 16384;
    constexpr int OFF_BLO = OFF_BHI + 16384;
    constexpr int SBYTES  = HAS_ALO ? 65536 : 49152;
    constexpr int PD      = NST - 1;     // prefetch distance

    extern __shared__ char smem[];
    const uint32_t sb = smem_u32(smem);
    __shared__ float Ys[33];

    const int tid = threadIdx.x;
    const int wid = tid >> 5, l = tid & 31;
    const int mTile = blockIdx.y * BM, nTile = blockIdx.x * BN;
    const int warpM = wid & 3, warpN = wid >> 2;   // 4x4 warp grid
    const int m0 = warpM * 32, n0 = warpN * 32;
    const int nK = K / BK;

    if (GELU && tid < 33) Ys[tid] = d_pwl_y[tid];

    // ---- ldmatrix address precompute ----
    const uint32_t rx = (uint32_t)((l & 7) << 4);
    uint32_t kpA[4], kpB[4];
    #pragma unroll
    for (int ks = 0; ks < 4; ks++) {
        kpA[ks] = ((uint32_t)(ks * 32 + ((l >> 4) << 4))) ^ rx;
        kpB[ks] = ((uint32_t)(ks * 32 + (((l >> 3) & 1) << 4))) ^ rx;
    }
    uint32_t aoff[2], boff[2];
    #pragma unroll
    for (int mt = 0; mt < 2; mt++) aoff[mt] = (uint32_t)((m0 + mt * 16 + (l & 15)) * 128);
    #pragma unroll
    for (int p = 0; p < 2; p++)
        boff[p] = (uint32_t)((n0 + p * 16 + ((l >> 4) << 3) + (l & 7)) * 128);

    float accm[2][4][4];   // master (RN FADD accumulation)
    float accc[2][4][4];   // cross terms (x2048; plain MMA accumulation)
    #pragma unroll
    for (int mt = 0; mt < 2; mt++)
        #pragma unroll
        for (int t = 0; t < 4; t++)
            #pragma unroll
            for (int j = 0; j < 4; j++) { accm[mt][t][j] = 0.0f; accc[mt][t][j] = 0.0f; }

    // ---- stage loader (512 threads: 2 chunks of 16B per 16KB tile) ----
    auto load_stage = [&](int kt, int s) {
        const uint32_t sbase = sb + s * SBYTES;
        const int k0 = kt * BK;
        #pragma unroll
        for (int i = 0; i < 2; i++) {
            int c = tid + i * NTHREADS;
            int r = c >> 3, cc = c & 7;
            uint32_t so = SWZ((uint32_t)(r * 128 + cc * 16));
            const __half* gA = A + (size_t)(mTile + r) * K + k0 + cc * 8;
            CP16(sbase + so, gA);
            if (HAS_ALO) {
                const __half* gAl = Alo + (size_t)(mTile + r) * K + k0 + cc * 8;
                CP16(sbase + OFF_ALO + so, gAl);
            }
            const __half* gB  = B   + (size_t)(nTile + r) * K + k0 + cc * 8;
            const __half* gBl = Blo + (size_t)(nTile + r) * K + k0 + cc * 8;
            CP16(sbase + OFF_BHI + so, gB);
            CP16(sbase + OFF_BLO + so, gBl);
        }
    };

    #pragma unroll
    for (int i = 0; i < PD; i++) { load_stage(i, i); CP_COMMIT(); }

    for (int kt = 0; kt < nK; kt++) {
        cp_wait<PD - 1>();
        __syncthreads();
        const int s = kt % NST;
        if (kt + PD < nK) load_stage(kt + PD, (kt + PD) % NST);
        CP_COMMIT();

        const uint32_t st = sb + s * SBYTES;
        #pragma unroll
        for (int ks = 0; ks < 4; ks++) {
            uint32_t ah[2][4], al[2][4];
            #pragma unroll
            for (int mt = 0; mt < 2; mt++) {
                ldsm4(ah[mt], st + aoff[mt] + kpA[ks]);
                if (HAS_ALO) ldsm4(al[mt], st + OFF_ALO + aoff[mt] + kpA[ks]);
            }
            #pragma unroll
            for (int p = 0; p < 2; p++) {
                uint32_t bh[4], bl[4];
                ldsm4(bh, st + OFF_BHI + boff[p] + kpB[ks]);
                ldsm4(bl, st + OFF_BLO + boff[p] + kpB[ks]);
                #pragma unroll
                for (int tt = 0; tt < 2; tt++) {
                    const int t = p * 2 + tt;
                    const uint32_t h0 = bh[tt * 2], h1 = bh[tt * 2 + 1];
                    const uint32_t l0 = bl[tt * 2], l1 = bl[tt * 2 + 1];
                    #pragma unroll
                    for (int mt = 0; mt < 2; mt++) {
                        float tacc[4];
                        mma16816_z(tacc, ah[mt], h0, h1);   // hi*hi, fresh fragment
                        accm[mt][t][0] += tacc[0];
                        accm[mt][t][1] += tacc[1];
                        accm[mt][t][2] += tacc[2];
                        accm[mt][t][3] += tacc[3];
                        mma16816(accc[mt][t], ah[mt], l0, l1);
                        if (HAS_ALO) mma16816(accc[mt][t], al[mt], h0, h1);
                    }
                }
            }
        }
    }

    // ---- epilogue: v = Dm + Dc/2048 + bias ----
    const float invS = 4.8828125e-4f;   // 1/2048
    const int rg = mTile + m0 + (l >> 2);
    const int cg = nTile + n0 + (l & 3) * 2;
    #pragma unroll
    for (int mt = 0; mt < 2; mt++) {
        const int r0r = rg + mt * 16;
        #pragma unroll
        for (int t = 0; t < 4; t++) {
            const int col = cg + t * 8;
            const float b0 = __ldg(bias + col), b1 = __ldg(bias + col + 1);
            float v0 = fmaf(accc[mt][t][0], invS, accm[mt][t][0]) + b0;
            float v1 = fmaf(accc[mt][t][1], invS, accm[mt][t][1]) + b1;
            float v2 = fmaf(accc[mt][t][2], invS, accm[mt][t][2]) + b0;
            float v3 = fmaf(accc[mt][t][3], invS, accm[mt][t][3]) + b1;
            if (GELU) {
                v0 = q8(gelu_pwl(q8(v0), Ys)); v1 = q8(gelu_pwl(q8(v1), Ys));
                v2 = q8(gelu_pwl(q8(v2), Ys)); v3 = q8(gelu_pwl(q8(v3), Ys));
                *(__half2*)(outH + (size_t)r0r * N + col) =
                    __halves2half2(__float2half_rn(v0), __float2half_rn(v1));
                *(__half2*)(outH + (size_t)(r0r + 8) * N + col) =
                    __halves2half2(__float2half_rn(v2), __float2half_rn(v3));
            } else {
                float2 o0 = {q8(v0), q8(v1)}, o1 = {q8(v2), q8(v3)};
                *(float2*)(outF + (size_t)r0r * N + col) = o0;
                *(float2*)(outF + (size_t)(r0r + 8) * N + col) = o1;
            }
        }
    }
}

extern "C" void kernel_launch(void* const* d_in, const int* in_sizes, int n_in,
                              void* d_out, int out_size)
{
    const float* x  = (const float*)d_in[0];
    const float* w1 = (const float*)d_in[1];
    const float* b1 = (const float*)d_in[2];
    const float* w2 = (const float*)d_in[3];
    const float* b2 = (const float*)d_in[4];
    float* out = (float*)d_out;

    __half *a1hi, *a1lo, *w1thi, *w1tlo, *hbuf, *w2thi, *w2tlo;
    cudaGetSymbolAddress((void**)&a1hi, g_a1hi);
    cudaGetSymbolAddress((void**)&a1lo, g_a1lo);
    cudaGetSymbolAddress((void**)&w1thi, g_w1thi);
    cudaGetSymbolAddress((void**)&w1tlo, g_w1tlo);
    cudaGetSymbolAddress((void**)&hbuf, g_hbuf);
    cudaGetSymbolAddress((void**)&w2thi, g_w2thi);
    cudaGetSymbolAddress((void**)&w2tlo, g_w2tlo);

    int n4 = M_ROWS * D_DIM / 4;
    split_x_kernel<<<(n4 + 255) / 256, 256>>>((const float4*)x, a1hi, a1lo, n4);
    transpose_split_kernel<<<dim3(F_DIM / 32, D_DIM / 32), dim3(32, 8)>>>(w1, w1thi, w1tlo, D_DIM, F_DIM);
    transpose_split_kernel<<<dim3(D_DIM / 32, F_DIM / 32), dim3(32, 8)>>>(w2, w2thi, w2tlo, F_DIM, D_DIM);

    constexpr int SMEM1 = 3 * 65536;       // 192 KB
    constexpr int SMEM2 = 4 * 49152;       // 192 KB
    cudaFuncSetAttribute((const void*)gemm_mma<true,  true,  3>,
                         cudaFuncAttributeMaxDynamicSharedMemorySize, SMEM1);
    cudaFuncSetAttribute((const void*)gemm_mma<false, false, 4>,
                         cudaFuncAttributeMaxDynamicSharedMemorySize, SMEM2);

    // GEMM1: [16384,1024] x [4096,1024]^T -> h (gelu+q8, fp16)
    gemm_mma<true, true, 3><<<dim3(F_DIM / BN, M_ROWS / BM), NTHREADS, SMEM1>>>(
        a1hi, a1lo, w1thi, w1tlo, b1, hbuf, nullptr, D_DIM, F_DIM);
    // GEMM2: [16384,4096] x [1024,4096]^T -> out (q8, f32)
    gemm_mma<false, false, 4><<<dim3(D_DIM / BN, M_ROWS / BM), NTHREADS, SMEM2>>>(
        hbuf, hbuf, w2thi, w2tlo, b2, nullptr, out, F_DIM, D_DIM);
}

// round 8
// speedup vs baseline: 1.0295x; 1.0295x over previous
#include <cuda_runtime.h>
#include <cuda_fp16.h>
#include <cstdint>
#include <cstddef>

// ============================================================================
// Quantized FFN via fp16-split warp-level mma.sync (HMMA) GEMMs.
//   GEMM1: h = q8(gelu_pwl(q8(x@w1+b1)))  -> h exact on q8 grid, stored fp16
//   GEMM2: out = q8(h@w2+b2)
// Split: hi=fp16(x), lo=fp16((x-hi)*2048).
// Main term:  tacc = Ahi*Bhi + 0 (f32 acc, per-MMA), master += tacc via RN FADD.
// Cross term: f16-ACCUMULATOR MMAs (2x rate); value/2048 makes f16 acc error
//             negligible (<1e-5 absolute after rescale).
// result = master + cross_f16/2048 + bias.
// ============================================================================

#define M_ROWS 16384
#define D_DIM  1024
#define F_DIM  4096

#define BM 128
#define BN 128
#define BK 64
#define NTHREADS 512

// ---------------- device scratch ----------------
__device__ __half g_a1hi [(size_t)M_ROWS * D_DIM];
__device__ __half g_a1lo [(size_t)M_ROWS * D_DIM];
__device__ __half g_w1thi[(size_t)F_DIM * D_DIM];
__device__ __half g_w1tlo[(size_t)F_DIM * D_DIM];
__device__ __half g_hbuf [(size_t)M_ROWS * F_DIM];
__device__ __half g_w2thi[(size_t)D_DIM * F_DIM];
__device__ __half g_w2tlo[(size_t)D_DIM * F_DIM];

__device__ float d_pwl_y[33] = {
    -1.2668497e-04f, -3.3156488e-04f, -8.1420185e-04f, -1.8753475e-03f,
    -4.0496940e-03f, -8.1943491e-03f, -1.5524163e-02f, -2.7505064e-02f,
    -4.5500264e-02f, -7.0103525e-02f, -1.0021080e-01f, -1.3206222e-01f,
    -1.5865525e-01f, -1.6997051e-01f, -1.5426877e-01f, -1.0032342e-01f,
     0.0000000e+00f,  1.4967658e-01f,  3.4573123e-01f,  5.8002949e-01f,
     8.4134475e-01f,  1.1179378e+00f,  1.3997892e+00f,  1.6798965e+00f,
     1.9544997e+00f,  2.2224949e+00f,  2.4844758e+00f,  2.7418056e+00f,
     2.9959503e+00f,  3.2481247e+00f,  3.4991858e+00f,  3.7496684e+00f,
     3.9998733e+00f
};

// ---------------- asm helpers ----------------
__device__ __forceinline__ uint32_t smem_u32(const void* p) {
    uint32_t a;
    asm("{ .reg .u64 t; cvta.to.shared.u64 t, %1; cvt.u32.u64 %0, t; }" : "=r"(a) : "l"(p));
    return a;
}
#define CP16(smem, gmem) \
    asm volatile("cp.async.cg.shared.global [%0], [%1], 16;" :: "r"(smem), "l"(gmem))
#define CP_COMMIT() asm volatile("cp.async.commit_group;" ::: "memory")
template<int N>
__device__ __forceinline__ void cp_wait() {
    asm volatile("cp.async.wait_group %0;" :: "n"(N) : "memory");
}

__device__ __forceinline__ void ldsm4(uint32_t* r, uint32_t addr) {
    asm volatile("ldmatrix.sync.aligned.m8n8.x4.shared.b16 {%0,%1,%2,%3}, [%4];"
        : "=r"(r[0]), "=r"(r[1]), "=r"(r[2]), "=r"(r[3]) : "r"(addr));
}
// d = a*b + 0, f32 accum (fresh fragment; caller FADDs into master with RN)
__device__ __forceinline__ void mma16816_z(float* d, const uint32_t* a, uint32_t b0, uint32_t b1) {
    asm volatile("mma.sync.aligned.m16n8k16.row.col.f32.f16.f16.f32 "
        "{%0,%1,%2,%3},{%4,%5,%6,%7},{%8,%9},{%10,%10,%10,%10};"
        : "=f"(d[0]), "=f"(d[1]), "=f"(d[2]), "=f"(d[3])
        : "r"(a[0]), "r"(a[1]), "r"(a[2]), "r"(a[3]), "r"(b0), "r"(b1), "f"(0.0f));
}
// c += a*b, f16 accumulator (2 b32 regs hold 4 halves) -- 2x rate
__device__ __forceinline__ void mma16816_h(uint32_t* c, const uint32_t* a, uint32_t b0, uint32_t b1) {
    asm volatile("mma.sync.aligned.m16n8k16.row.col.f16.f16.f16.f16 "
        "{%0,%1},{%2,%3,%4,%5},{%6,%7},{%0,%1};"
        : "+r"(c[0]), "+r"(c[1])
        : "r"(a[0]), "r"(a[1]), "r"(a[2]), "r"(a[3]), "r"(b0), "r"(b1));
}
#define SWZ(o) ((o) ^ (((o) >> 3) & 0x70))

__device__ __forceinline__ float q8(float v) { return rintf(v * 256.0f) * 0.00390625f; }

__device__ __forceinline__ float gelu_pwl(float v, const float* Ys) {
    if (v > 4.0f) return v;
    if (v < -4.0f) return 0.0f;
    float u = (v + 4.0f) * 4.0f;      // exact on q8 grid
    int idx = (int)u; if (idx > 31) idx = 31;
    float f = u - (float)idx;
    float y0 = Ys[idx], y1 = Ys[idx + 1];
    return fmaf(f, y1 - y0, y0);
}

// ---------------- prepass ----------------
__device__ __forceinline__ void split1(float x, __half& h, __half& l) {
    h = __float2half_rn(x);
    l = __float2half_rn((x - __half2float(h)) * 2048.0f);
}
__global__ void split_x_kernel(const float4* __restrict__ in, __half* __restrict__ hi,
                               __half* __restrict__ lo, int n4) {
    int i = blockIdx.x * blockDim.x + threadIdx.x;
    if (i >= n4) return;
    float4 v = in[i];
    __half h[4], l[4];
    split1(v.x, h[0], l[0]); split1(v.y, h[1], l[1]);
    split1(v.z, h[2], l[2]); split1(v.w, h[3], l[3]);
    *(uint2*)(hi + (size_t)i * 4) = *(uint2*)h;
    *(uint2*)(lo + (size_t)i * 4) = *(uint2*)l;
}
// in: [R, C] f32 -> hi/lo: [C, R] fp16 (transpose + split)
__global__ void transpose_split_kernel(const float* __restrict__ in, __half* __restrict__ hi,
                                       __half* __restrict__ lo, int R, int C) {
    __shared__ float t[32][33];
    int c0 = blockIdx.x * 32, r0 = blockIdx.y * 32;
    int tx = threadIdx.x, ty = threadIdx.y;   // 32 x 8
    #pragma unroll
    for (int i = 0; i < 32; i += 8)
        t[ty + i][tx] = in[(size_t)(r0 + ty + i) * C + c0 + tx];
    __syncthreads();
    #pragma unroll
    for (int i = 0; i < 32; i += 8) {
        __half h, l; split1(t[tx][ty + i], h, l);
        size_t o = (size_t)(c0 + ty + i) * R + r0 + tx;
        hi[o] = h; lo[o] = l;
    }
}

// ---------------- main GEMM ----------------
// C[M,N] = A[M,K] @ B[N,K]^T (+bias, q8, optional PWL-GELU)
// 16 warps in 4x4 grid, warp tile 32x32.
// Stage layout: Ahi[16K] [Alo 16K if HAS_ALO] Bhi[16K] Blo[16K]
template<bool HAS_ALO, bool GELU, int NST>
__global__ void __launch_bounds__(NTHREADS, 1)
gemm_mma(const __half* __restrict__ A, const __half* __restrict__ Alo,
         const __half* __restrict__ B, const __half* __restrict__ Blo,
         const float* __restrict__ bias,
         __half* __restrict__ outH, float* __restrict__ outF,
         int K, int N)
{
    constexpr int OFF_ALO = 16384;
    constexpr int OFF_BHI = HAS_ALO ? 32768 : 16384;
    constexpr int OFF_BLO = OFF_BHI + 16384;
    constexpr int SBYTES  = HAS_ALO ? 65536 : 49152;
    constexpr int PD      = NST - 1;     // prefetch distance

    extern __shared__ char smem[];
    const uint32_t sb = smem_u32(smem);
    __shared__ float Ys[33];

    const int tid = threadIdx.x;
    const int wid = tid >> 5, l = tid & 31;
    const int mTile = blockIdx.y * BM, nTile = blockIdx.x * BN;
    const int warpM = wid & 3, warpN = wid >> 2;   // 4x4 warp grid
    const int m0 = warpM * 32, n0 = warpN * 32;
    const int nK = K / BK;

    if (GELU && tid < 33) Ys[tid] = d_pwl_y[tid];

    // ---- ldmatrix address precompute ----
    const uint32_t rx = (uint32_t)((l & 7) << 4);
    uint32_t kpA[4], kpB[4];
    #pragma unroll
    for (int ks = 0; ks < 4; ks++) {
        kpA[ks] = ((uint32_t)(ks * 32 + ((l >> 4) << 4))) ^ rx;
        kpB[ks] = ((uint32_t)(ks * 32 + (((l >> 3) & 1) << 4))) ^ rx;
    }
    uint32_t aoff[2], boff[2];
    #pragma unroll
    for (int mt = 0; mt < 2; mt++) aoff[mt] = (uint32_t)((m0 + mt * 16 + (l & 15)) * 128);
    #pragma unroll
    for (int p = 0; p < 2; p++)
        boff[p] = (uint32_t)((n0 + p * 16 + ((l >> 4) << 3) + (l & 7)) * 128);

    float    accm[2][4][4];   // master (f32, RN FADD accumulation of hi*hi)
    uint32_t accx[2][4][2];   // cross terms (x2048) in f16 accumulators
    #pragma unroll
    for (int mt = 0; mt < 2; mt++)
        #pragma unroll
        for (int t = 0; t < 4; t++) {
            #pragma unroll
            for (int j = 0; j < 4; j++) accm[mt][t][j] = 0.0f;
            accx[mt][t][0] = 0u; accx[mt][t][1] = 0u;
        }

    // ---- stage loader (512 threads: 2 chunks of 16B per 16KB tile) ----
    auto load_stage = [&](int kt, int s) {
        const uint32_t sbase = sb + s * SBYTES;
        const int k0 = kt * BK;
        #pragma unroll
        for (int i = 0; i < 2; i++) {
            int c = tid + i * NTHREADS;
            int r = c >> 3, cc = c & 7;
            uint32_t so = SWZ((uint32_t)(r * 128 + cc * 16));
            const __half* gA = A + (size_t)(mTile + r) * K + k0 + cc * 8;
            CP16(sbase + so, gA);
            if (HAS_ALO) {
                const __half* gAl = Alo + (size_t)(mTile + r) * K + k0 + cc * 8;
                CP16(sbase + OFF_ALO + so, gAl);
            }
            const __half* gB  = B   + (size_t)(nTile + r) * K + k0 + cc * 8;
            const __half* gBl = Blo + (size_t)(nTile + r) * K + k0 + cc * 8;
            CP16(sbase + OFF_BHI + so, gB);
            CP16(sbase + OFF_BLO + so, gBl);
        }
    };

    #pragma unroll
    for (int i = 0; i < PD; i++) { load_stage(i, i); CP_COMMIT(); }

    for (int kt = 0; kt < nK; kt++) {
        cp_wait<PD - 1>();
        __syncthreads();
        const int s = kt % NST;
        if (kt + PD < nK) load_stage(kt + PD, (kt + PD) % NST);
        CP_COMMIT();

        const uint32_t st = sb + s * SBYTES;
        #pragma unroll
        for (int ks = 0; ks < 4; ks++) {
            uint32_t ah[2][4], al[2][4];
            #pragma unroll
            for (int mt = 0; mt < 2; mt++) {
                ldsm4(ah[mt], st + aoff[mt] + kpA[ks]);
                if (HAS_ALO) ldsm4(al[mt], st + OFF_ALO + aoff[mt] + kpA[ks]);
            }
            #pragma unroll
            for (int p = 0; p < 2; p++) {
                uint32_t bh[4], bl[4];
                ldsm4(bh, st + OFF_BHI + boff[p] + kpB[ks]);
                ldsm4(bl, st + OFF_BLO + boff[p] + kpB[ks]);
                #pragma unroll
                for (int tt = 0; tt < 2; tt++) {
                    const int t = p * 2 + tt;
                    const uint32_t h0 = bh[tt * 2], h1 = bh[tt * 2 + 1];
                    const uint32_t l0 = bl[tt * 2], l1 = bl[tt * 2 + 1];
                    #pragma unroll
                    for (int mt = 0; mt < 2; mt++) {
                        float tacc[4];
                        mma16816_z(tacc, ah[mt], h0, h1);   // hi*hi f32, fresh fragment
                        accm[mt][t][0] += tacc[0];
                        accm[mt][t][1] += tacc[1];
                        accm[mt][t][2] += tacc[2];
                        accm[mt][t][3] += tacc[3];
                        mma16816_h(accx[mt][t], ah[mt], l0, l1);              // hi*lo (f16 acc)
                        if (HAS_ALO) mma16816_h(accx[mt][t], al[mt], h0, h1); // lo*hi (f16 acc)
                    }
                }
            }
        }
    }

    // ---- epilogue: v = Dm + cross_f16/2048 + bias ----
    const float invS = 4.8828125e-4f;   // 1/2048
    const int rg = mTile + m0 + (l >> 2);
    const int cg = nTile + n0 + (l & 3) * 2;
    #pragma unroll
    for (int mt = 0; mt < 2; mt++) {
        const int r0r = rg + mt * 16;
        #pragma unroll
        for (int t = 0; t < 4; t++) {
            const int col = cg + t * 8;
            const float b0 = __ldg(bias + col), b1 = __ldg(bias + col + 1);
            const __half2 c01 = *(const __half2*)&accx[mt][t][0];
            const __half2 c23 = *(const __half2*)&accx[mt][t][1];
            float v0 = fmaf(__half2float(__low2half(c01)),  invS, accm[mt][t][0]) + b0;
            float v1 = fmaf(__half2float(__high2half(c01)), invS, accm[mt][t][1]) + b1;
            float v2 = fmaf(__half2float(__low2half(c23)),  invS, accm[mt][t][2]) + b0;
            float v3 = fmaf(__half2float(__high2half(c23)), invS, accm[mt][t][3]) + b1;
            if (GELU) {
                v0 = q8(gelu_pwl(q8(v0), Ys)); v1 = q8(gelu_pwl(q8(v1), Ys));
                v2 = q8(gelu_pwl(q8(v2), Ys)); v3 = q8(gelu_pwl(q8(v3), Ys));
                *(__half2*)(outH + (size_t)r0r * N + col) =
                    __halves2half2(__float2half_rn(v0), __float2half_rn(v1));
                *(__half2*)(outH + (size_t)(r0r + 8) * N + col) =
                    __halves2half2(__float2half_rn(v2), __float2half_rn(v3));
            } else {
                float2 o0 = {q8(v0), q8(v1)}, o1 = {q8(v2), q8(v3)};
                *(float2*)(outF + (size_t)r0r * N + col) = o0;
                *(float2*)(outF + (size_t)(r0r + 8) * N + col) = o1;
            }
        }
    }
}

extern "C" void kernel_launch(void* const* d_in, const int* in_sizes, int n_in,
                              void* d_out, int out_size)
{
    const float* x  = (const float*)d_in[0];
    const float* w1 = (const float*)d_in[1];
    const float* b1 = (const float*)d_in[2];
    const float* w2 = (const float*)d_in[3];
    const float* b2 = (const float*)d_in[4];
    float* out = (float*)d_out;

    __half *a1hi, *a1lo, *w1thi, *w1tlo, *hbuf, *w2thi, *w2tlo;
    cudaGetSymbolAddress((void**)&a1hi, g_a1hi);
    cudaGetSymbolAddress((void**)&a1lo, g_a1lo);
    cudaGetSymbolAddress((void**)&w1thi, g_w1thi);
    cudaGetSymbolAddress((void**)&w1tlo, g_w1tlo);
    cudaGetSymbolAddress((void**)&hbuf, g_hbuf);
    cudaGetSymbolAddress((void**)&w2thi, g_w2thi);
    cudaGetSymbolAddress((void**)&w2tlo, g_w2tlo);

    int n4 = M_ROWS * D_DIM / 4;
    split_x_kernel<<<(n4 + 255) / 256, 256>>>((const float4*)x, a1hi, a1lo, n4);
    transpose_split_kernel<<<dim3(F_DIM / 32, D_DIM / 32), dim3(32, 8)>>>(w1, w1thi, w1tlo, D_DIM, F_DIM);
    transpose_split_kernel<<<dim3(D_DIM / 32, F_DIM / 32), dim3(32, 8)>>>(w2, w2thi, w2tlo, F_DIM, D_DIM);

    constexpr int SMEM1 = 3 * 65536;       // 192 KB
    constexpr int SMEM2 = 4 * 49152;       // 192 KB
    cudaFuncSetAttribute((const void*)gemm_mma<true,  true,  3>,
                         cudaFuncAttributeMaxDynamicSharedMemorySize, SMEM1);
    cudaFuncSetAttribute((const void*)gemm_mma<false, false, 4>,
                         cudaFuncAttributeMaxDynamicSharedMemorySize, SMEM2);

    // GEMM1: [16384,1024] x [4096,1024]^T -> h (gelu+q8, fp16)
    gemm_mma<true, true, 3><<<dim3(F_DIM / BN, M_ROWS / BM), NTHREADS, SMEM1>>>(
        a1hi, a1lo, w1thi, w1tlo, b1, hbuf, nullptr, D_DIM, F_DIM);
    // GEMM2: [16384,4096] x [1024,4096]^T -> out (q8, f32)
    gemm_mma<false, false, 4><<<dim3(D_DIM / BN, M_ROWS / BM), NTHREADS, SMEM2>>>(
        hbuf, hbuf, w2thi, w2tlo, b2, nullptr, out, F_DIM, D_DIM);
}

// round 9
// speedup vs baseline: 1.0602x; 1.0298x over previous
#include <cuda_runtime.h>
#include <cuda_fp16.h>
#include <cstdint>
#include <cstddef>

// ============================================================================
// Quantized FFN via fp16-split warp-level mma.sync (HMMA) GEMMs.
//   GEMM1: h = q8(gelu_pwl(q8(x@w1+b1)))  -> h exact on q8 grid, stored fp16
//   GEMM2: out = q8(h@w2+b2)
// Split: hi=fp16(x), lo=fp16((x-hi)*2048).
// Main term: chain-of-2 MMA (z then accumulate) -> 4-FADD RN flush to master.
// Cross term: f16-accumulator MMAs; /2048 rescale makes error negligible.
// result = master + cross_f16/2048 + bias.
// R9: 8 warps @ 32x64 warp tile (R4 shape), paired-MMA flush.
// ============================================================================

#define M_ROWS 16384
#define D_DIM  1024
#define F_DIM  4096

#define BM 128
#define BN 128
#define BK 64
#define NTHREADS 256

// ---------------- device scratch ----------------
__device__ __half g_a1hi [(size_t)M_ROWS * D_DIM];
__device__ __half g_a1lo [(size_t)M_ROWS * D_DIM];
__device__ __half g_w1thi[(size_t)F_DIM * D_DIM];
__device__ __half g_w1tlo[(size_t)F_DIM * D_DIM];
__device__ __half g_hbuf [(size_t)M_ROWS * F_DIM];
__device__ __half g_w2thi[(size_t)D_DIM * F_DIM];
__device__ __half g_w2tlo[(size_t)D_DIM * F_DIM];

__device__ float d_pwl_y[33] = {
    -1.2668497e-04f, -3.3156488e-04f, -8.1420185e-04f, -1.8753475e-03f,
    -4.0496940e-03f, -8.1943491e-03f, -1.5524163e-02f, -2.7505064e-02f,
    -4.5500264e-02f, -7.0103525e-02f, -1.0021080e-01f, -1.3206222e-01f,
    -1.5865525e-01f, -1.6997051e-01f, -1.5426877e-01f, -1.0032342e-01f,
     0.0000000e+00f,  1.4967658e-01f,  3.4573123e-01f,  5.8002949e-01f,
     8.4134475e-01f,  1.1179378e+00f,  1.3997892e+00f,  1.6798965e+00f,
     1.9544997e+00f,  2.2224949e+00f,  2.4844758e+00f,  2.7418056e+00f,
     2.9959503e+00f,  3.2481247e+00f,  3.4991858e+00f,  3.7496684e+00f,
     3.9998733e+00f
};

// ---------------- asm helpers ----------------
__device__ __forceinline__ uint32_t smem_u32(const void* p) {
    uint32_t a;
    asm("{ .reg .u64 t; cvta.to.shared.u64 t, %1; cvt.u32.u64 %0, t; }" : "=r"(a) : "l"(p));
    return a;
}
#define CP16(smem, gmem) \
    asm volatile("cp.async.cg.shared.global [%0], [%1], 16;" :: "r"(smem), "l"(gmem))
#define CP_COMMIT() asm volatile("cp.async.commit_group;" ::: "memory")
template<int N>
__device__ __forceinline__ void cp_wait() {
    asm volatile("cp.async.wait_group %0;" :: "n"(N) : "memory");
}

__device__ __forceinline__ void ldsm4(uint32_t* r, uint32_t addr) {
    asm volatile("ldmatrix.sync.aligned.m8n8.x4.shared.b16 {%0,%1,%2,%3}, [%4];"
        : "=r"(r[0]), "=r"(r[1]), "=r"(r[2]), "=r"(r[3]) : "r"(addr));
}
// c += a*b, f32 accumulator (in-place)
__device__ __forceinline__ void mma16816(float* c, const uint32_t* a, uint32_t b0, uint32_t b1) {
    asm volatile("mma.sync.aligned.m16n8k16.row.col.f32.f16.f16.f32 "
        "{%0,%1,%2,%3},{%4,%5,%6,%7},{%8,%9},{%0,%1,%2,%3};"
        : "+f"(c[0]), "+f"(c[1]), "+f"(c[2]), "+f"(c[3])
        : "r"(a[0]), "r"(a[1]), "r"(a[2]), "r"(a[3]), "r"(b0), "r"(b1));
}
// d = a*b + 0, f32 accum (fresh fragment)
__device__ __forceinline__ void mma16816_z(float* d, const uint32_t* a, uint32_t b0, uint32_t b1) {
    asm volatile("mma.sync.aligned.m16n8k16.row.col.f32.f16.f16.f32 "
        "{%0,%1,%2,%3},{%4,%5,%6,%7},{%8,%9},{%10,%10,%10,%10};"
        : "=f"(d[0]), "=f"(d[1]), "=f"(d[2]), "=f"(d[3])
        : "r"(a[0]), "r"(a[1]), "r"(a[2]), "r"(a[3]), "r"(b0), "r"(b1), "f"(0.0f));
}
// c += a*b, f16 accumulator (2 b32 regs hold 4 halves)
__device__ __forceinline__ void mma16816_h(uint32_t* c, const uint32_t* a, uint32_t b0, uint32_t b1) {
    asm volatile("mma.sync.aligned.m16n8k16.row.col.f16.f16.f16.f16 "
        "{%0,%1},{%2,%3,%4,%5},{%6,%7},{%0,%1};"
        : "+r"(c[0]), "+r"(c[1])
        : "r"(a[0]), "r"(a[1]), "r"(a[2]), "r"(a[3]), "r"(b0), "r"(b1));
}
#define SWZ(o) ((o) ^ (((o) >> 3) & 0x70))

__device__ __forceinline__ float q8(float v) { return rintf(v * 256.0f) * 0.00390625f; }

__device__ __forceinline__ float gelu_pwl(float v, const float* Ys) {
    if (v > 4.0f) return v;
    if (v < -4.0f) return 0.0f;
    float u = (v + 4.0f) * 4.0f;      // exact on q8 grid
    int idx = (int)u; if (idx > 31) idx = 31;
    float f = u - (float)idx;
    float y0 = Ys[idx], y1 = Ys[idx + 1];
    return fmaf(f, y1 - y0, y0);
}

// ---------------- prepass ----------------
__device__ __forceinline__ void split1(float x, __half& h, __half& l) {
    h = __float2half_rn(x);
    l = __float2half_rn((x - __half2float(h)) * 2048.0f);
}
__global__ void split_x_kernel(const float4* __restrict__ in, __half* __restrict__ hi,
                               __half* __restrict__ lo, int n4) {
    int i = blockIdx.x * blockDim.x + threadIdx.x;
    if (i >= n4) return;
    float4 v = in[i];
    __half h[4], l[4];
    split1(v.x, h[0], l[0]); split1(v.y, h[1], l[1]);
    split1(v.z, h[2], l[2]); split1(v.w, h[3], l[3]);
    *(uint2*)(hi + (size_t)i * 4) = *(uint2*)h;
    *(uint2*)(lo + (size_t)i * 4) = *(uint2*)l;
}
// in: [R, C] f32 -> hi/lo: [C, R] fp16 (transpose + split)
__global__ void transpose_split_kernel(const float* __restrict__ in, __half* __restrict__ hi,
                                       __half* __restrict__ lo, int R, int C) {
    __shared__ float t[32][33];
    int c0 = blockIdx.x * 32, r0 = blockIdx.y * 32;
    int tx = threadIdx.x, ty = threadIdx.y;   // 32 x 8
    #pragma unroll
    for (int i = 0; i < 32; i += 8)
        t[ty + i][tx] = in[(size_t)(r0 + ty + i) * C + c0 + tx];
    __syncthreads();
    #pragma unroll
    for (int i = 0; i < 32; i += 8) {
        __half h, l; split1(t[tx][ty + i], h, l);
        size_t o = (size_t)(c0 + ty + i) * R + r0 + tx;
        hi[o] = h; lo[o] = l;
    }
}

// ---------------- main GEMM ----------------
// C[M,N] = A[M,K] @ B[N,K]^T (+bias, q8, optional PWL-GELU)
// 8 warps, 4x2 grid, warp tile 32x64.
// Stage layout: Ahi[16K] [Alo 16K if HAS_ALO] Bhi[16K] Blo[16K]
template<bool HAS_ALO, bool GELU, int NST>
__global__ void __launch_bounds__(NTHREADS, 1)
gemm_mma(const __half* __restrict__ A, const __half* __restrict__ Alo,
         const __half* __restrict__ B, const __half* __restrict__ Blo,
         const float* __restrict__ bias,
         __half* __restrict__ outH, float* __restrict__ outF,
         int K, int N)
{
    constexpr int OFF_ALO = 16384;
    constexpr int OFF_BHI = HAS_ALO ? 32768 : 16384;
    constexpr int OFF_BLO = OFF_BHI + 16384;
    constexpr int SBYTES  = HAS_ALO ? 65536 : 49152;
    constexpr int PD      = NST - 1;     // prefetch distance

    extern __shared__ char smem[];
    const uint32_t sb = smem_u32(smem);
    __shared__ float Ys[33];

    const int tid = threadIdx.x;
    const int wid = tid >> 5, l = tid & 31;
    const int mTile = blockIdx.y * BM, nTile = blockIdx.x * BN;
    const int warpM = wid & 3, warpN = wid >> 2;   // 4x2 warp grid
    const int m0 = warpM * 32, n0 = warpN * 64;
    const int nK = K / BK;

    if (GELU && tid < 33) Ys[tid] = d_pwl_y[tid];

    // ---- ldmatrix address precompute ----
    const uint32_t rx = (uint32_t)((l & 7) << 4);
    uint32_t kpA[4], kpB[4];
    #pragma unroll
    for (int ks = 0; ks < 4; ks++) {
        kpA[ks] = ((uint32_t)(ks * 32 + ((l >> 4) << 4))) ^ rx;
        kpB[ks] = ((uint32_t)(ks * 32 + (((l >> 3) & 1) << 4))) ^ rx;
    }
    uint32_t aoff[2], boff[4];
    #pragma unroll
    for (int mt = 0; mt < 2; mt++) aoff[mt] = (uint32_t)((m0 + mt * 16 + (l & 15)) * 128);
    #pragma unroll
    for (int p = 0; p < 4; p++)
        boff[p] = (uint32_t)((n0 + p * 16 + ((l >> 4) << 3) + (l & 7)) * 128);

    float    accm[2][8][4];   // master (f32, RN FADD of chained pairs)
    uint32_t accx[2][8][2];   // cross terms (x2048) in f16 accumulators
    #pragma unroll
    for (int mt = 0; mt < 2; mt++)
        #pragma unroll
        for (int t = 0; t < 8; t++) {
            #pragma unroll
            for (int j = 0; j < 4; j++) accm[mt][t][j] = 0.0f;
            accx[mt][t][0] = 0u; accx[mt][t][1] = 0u;
        }

    // ---- stage loader (256 threads: 4 chunks of 16B per 16KB tile) ----
    auto load_stage = [&](int kt, int s) {
        const uint32_t sbase = sb + s * SBYTES;
        const int k0 = kt * BK;
        #pragma unroll
        for (int i = 0; i < 4; i++) {
            int c = tid + i * NTHREADS;
            int r = c >> 3, cc = c & 7;
            uint32_t so = SWZ((uint32_t)(r * 128 + cc * 16));
            const __half* gA = A + (size_t)(mTile + r) * K + k0 + cc * 8;
            CP16(sbase + so, gA);
            if (HAS_ALO) {
                const __half* gAl = Alo + (size_t)(mTile + r) * K + k0 + cc * 8;
                CP16(sbase + OFF_ALO + so, gAl);
            }
            const __half* gB  = B   + (size_t)(nTile + r) * K + k0 + cc * 8;
            const __half* gBl = Blo + (size_t)(nTile + r) * K + k0 + cc * 8;
            CP16(sbase + OFF_BHI + so, gB);
            CP16(sbase + OFF_BLO + so, gBl);
        }
    };

    #pragma unroll
    for (int i = 0; i < PD; i++) { load_stage(i, i); CP_COMMIT(); }

    for (int kt = 0; kt < nK; kt++) {
        cp_wait<PD - 1>();
        __syncthreads();
        const int s = kt % NST;
        if (kt + PD < nK) load_stage(kt + PD, (kt + PD) % NST);
        CP_COMMIT();

        const uint32_t st = sb + s * SBYTES;
        // two half-steps of 2 consecutive ks each; main term chains the pair
        #pragma unroll
        for (int ks2 = 0; ks2 < 2; ks2++) {
            uint32_t ah[2][2][4], al[2][2][4];   // [mt][ksl]
            #pragma unroll
            for (int mt = 0; mt < 2; mt++)
                #pragma unroll
                for (int ksl = 0; ksl < 2; ksl++) {
                    const int ks = ks2 * 2 + ksl;
                    ldsm4(ah[mt][ksl], st + aoff[mt] + kpA[ks]);
                    if (HAS_ALO) ldsm4(al[mt][ksl], st + OFF_ALO + aoff[mt] + kpA[ks]);
                }
            #pragma unroll
            for (int p = 0; p < 4; p++) {
                uint32_t bh[2][4], bl[2][4];     // [ksl]
                #pragma unroll
                for (int ksl = 0; ksl < 2; ksl++) {
                    const int ks = ks2 * 2 + ksl;
                    ldsm4(bh[ksl], st + OFF_BHI + boff[p] + kpB[ks]);
                    ldsm4(bl[ksl], st + OFF_BLO + boff[p] + kpB[ks]);
                }
                #pragma unroll
                for (int tt = 0; tt < 2; tt++) {
                    const int t = p * 2 + tt;
                    #pragma unroll
                    for (int mt = 0; mt < 2; mt++) {
                        float tacc[4];
                        // main: chained pair, then RN flush
                        mma16816_z(tacc, ah[mt][0], bh[0][tt * 2], bh[0][tt * 2 + 1]);
                        mma16816  (tacc, ah[mt][1], bh[1][tt * 2], bh[1][tt * 2 + 1]);
                        accm[mt][t][0] += tacc[0];
                        accm[mt][t][1] += tacc[1];
                        accm[mt][t][2] += tacc[2];
                        accm[mt][t][3] += tacc[3];
                        // cross: f16 accumulators
                        mma16816_h(accx[mt][t], ah[mt][0], bl[0][tt * 2], bl[0][tt * 2 + 1]);
                        mma16816_h(accx[mt][t], ah[mt][1], bl[1][tt * 2], bl[1][tt * 2 + 1]);
                        if (HAS_ALO) {
                            mma16816_h(accx[mt][t], al[mt][0], bh[0][tt * 2], bh[0][tt * 2 + 1]);
                            mma16816_h(accx[mt][t], al[mt][1], bh[1][tt * 2], bh[1][tt * 2 + 1]);
                        }
                    }
                }
            }
        }
    }

    // ---- epilogue: v = Dm + cross_f16/2048 + bias ----
    const float invS = 4.8828125e-4f;   // 1/2048
    const int rg = mTile + m0 + (l >> 2);
    const int cg = nTile + n0 + (l & 3) * 2;
    #pragma unroll
    for (int mt = 0; mt < 2; mt++) {
        const int r0r = rg + mt * 16;
        #pragma unroll
        for (int t = 0; t < 8; t++) {
            const int col = cg + t * 8;
            const float b0 = __ldg(bias + col), b1 = __ldg(bias + col + 1);
            const __half2 c01 = *(const __half2*)&accx[mt][t][0];
            const __half2 c23 = *(const __half2*)&accx[mt][t][1];
            float v0 = fmaf(__half2float(__low2half(c01)),  invS, accm[mt][t][0]) + b0;
            float v1 = fmaf(__half2float(__high2half(c01)), invS, accm[mt][t][1]) + b1;
            float v2 = fmaf(__half2float(__low2half(c23)),  invS, accm[mt][t][2]) + b0;
            float v3 = fmaf(__half2float(__high2half(c23)), invS, accm[mt][t][3]) + b1;
            if (GELU) {
                v0 = q8(gelu_pwl(q8(v0), Ys)); v1 = q8(gelu_pwl(q8(v1), Ys));
                v2 = q8(gelu_pwl(q8(v2), Ys)); v3 = q8(gelu_pwl(q8(v3), Ys));
                *(__half2*)(outH + (size_t)r0r * N + col) =
                    __halves2half2(__float2half_rn(v0), __float2half_rn(v1));
                *(__half2*)(outH + (size_t)(r0r + 8) * N + col) =
                    __halves2half2(__float2half_rn(v2), __float2half_rn(v3));
            } else {
                float2 o0 = {q8(v0), q8(v1)}, o1 = {q8(v2), q8(v3)};
                *(float2*)(outF + (size_t)r0r * N + col) = o0;
                *(float2*)(outF + (size_t)(r0r + 8) * N + col) = o1;
            }
        }
    }
}

extern "C" void kernel_launch(void* const* d_in, const int* in_sizes, int n_in,
                              void* d_out, int out_size)
{
    const float* x  = (const float*)d_in[0];
    const float* w1 = (const float*)d_in[1];
    const float* b1 = (const float*)d_in[2];
    const float* w2 = (const float*)d_in[3];
    const float* b2 = (const float*)d_in[4];
    float* out = (float*)d_out;

    __half *a1hi, *a1lo, *w1thi, *w1tlo, *hbuf, *w2thi, *w2tlo;
    cudaGetSymbolAddress((void**)&a1hi, g_a1hi);
    cudaGetSymbolAddress((void**)&a1lo, g_a1lo);
    cudaGetSymbolAddress((void**)&w1thi, g_w1thi);
    cudaGetSymbolAddress((void**)&w1tlo, g_w1tlo);
    cudaGetSymbolAddress((void**)&hbuf, g_hbuf);
    cudaGetSymbolAddress((void**)&w2thi, g_w2thi);
    cudaGetSymbolAddress((void**)&w2tlo, g_w2tlo);

    int n4 = M_ROWS * D_DIM / 4;
    split_x_kernel<<<(n4 + 255) / 256, 256>>>((const float4*)x, a1hi, a1lo, n4);
    transpose_split_kernel<<<dim3(F_DIM / 32, D_DIM / 32), dim3(32, 8)>>>(w1, w1thi, w1tlo, D_DIM, F_DIM);
    transpose_split_kernel<<<dim3(D_DIM / 32, F_DIM / 32), dim3(32, 8)>>>(w2, w2thi, w2tlo, F_DIM, D_DIM);

    constexpr int SMEM1 = 3 * 65536;       // 192 KB
    constexpr int SMEM2 = 4 * 49152;       // 192 KB
    cudaFuncSetAttribute((const void*)gemm_mma<true,  true,  3>,
                         cudaFuncAttributeMaxDynamicSharedMemorySize, SMEM1);
    cudaFuncSetAttribute((const void*)gemm_mma<false, false, 4>,
                         cudaFuncAttributeMaxDynamicSharedMemorySize, SMEM2);

    // GEMM1: [16384,1024] x [4096,1024]^T -> h (gelu+q8, fp16)
    gemm_mma<true, true, 3><<<dim3(F_DIM / BN, M_ROWS / BM), NTHREADS, SMEM1>>>(
        a1hi, a1lo, w1thi, w1tlo, b1, hbuf, nullptr, D_DIM, F_DIM);
    // GEMM2: [16384,4096] x [1024,4096]^T -> out (q8, f32)
    gemm_mma<false, false, 4><<<dim3(D_DIM / BN, M_ROWS / BM), NTHREADS, SMEM2>>>(
        hbuf, hbuf, w2thi, w2tlo, b2, nullptr, out, F_DIM, D_DIM);
}

// round 10
// speedup vs baseline: 1.0776x; 1.0164x over previous
#include <cuda_runtime.h>
#include <cuda_fp16.h>
#include <cstdint>
#include <cstddef>

// ============================================================================
// Quantized FFN via fp16-split warp-level mma.sync (HMMA) GEMMs.
//   GEMM1: h = q8(gelu_pwl(q8(x@w1+b1)))  -> h exact on q8 grid, stored fp16
//   GEMM2: out = q8(h@w2+b2)
// Split: hi=fp16(x), lo=fp16((x-hi)*2048).
// GEMM1 main: PLAIN f32 MMA chain (64 RZ adds; bias ~1.5e-4, tolerable).
// GEMM2 main: chain-2 z-MMA + RN FADD flush (kills the dominant 256-add bias).
// Cross terms (both): f16-accumulator MMAs; /2048 rescale -> error negligible.
// result = main + cross_f16/2048 + bias.
// ============================================================================

#define M_ROWS 16384
#define D_DIM  1024
#define F_DIM  4096

#define BM 128
#define BN 128
#define BK 64
#define NTHREADS 256

// ---------------- device scratch ----------------
__device__ __half g_a1hi [(size_t)M_ROWS * D_DIM];
__device__ __half g_a1lo [(size_t)M_ROWS * D_DIM];
__device__ __half g_w1thi[(size_t)F_DIM * D_DIM];
__device__ __half g_w1tlo[(size_t)F_DIM * D_DIM];
__device__ __half g_hbuf [(size_t)M_ROWS * F_DIM];
__device__ __half g_w2thi[(size_t)D_DIM * F_DIM];
__device__ __half g_w2tlo[(size_t)D_DIM * F_DIM];

__device__ float d_pwl_y[33] = {
    -1.2668497e-04f, -3.3156488e-04f, -8.1420185e-04f, -1.8753475e-03f,
    -4.0496940e-03f, -8.1943491e-03f, -1.5524163e-02f, -2.7505064e-02f,
    -4.5500264e-02f, -7.0103525e-02f, -1.0021080e-01f, -1.3206222e-01f,
    -1.5865525e-01f, -1.6997051e-01f, -1.5426877e-01f, -1.0032342e-01f,
     0.0000000e+00f,  1.4967658e-01f,  3.4573123e-01f,  5.8002949e-01f,
     8.4134475e-01f,  1.1179378e+00f,  1.3997892e+00f,  1.6798965e+00f,
     1.9544997e+00f,  2.2224949e+00f,  2.4844758e+00f,  2.7418056e+00f,
     2.9959503e+00f,  3.2481247e+00f,  3.4991858e+00f,  3.7496684e+00f,
     3.9998733e+00f
};

// ---------------- asm helpers ----------------
__device__ __forceinline__ uint32_t smem_u32(const void* p) {
    uint32_t a;
    asm("{ .reg .u64 t; cvta.to.shared.u64 t, %1; cvt.u32.u64 %0, t; }" : "=r"(a) : "l"(p));
    return a;
}
#define CP16(smem, gmem) \
    asm volatile("cp.async.cg.shared.global [%0], [%1], 16;" :: "r"(smem), "l"(gmem))
#define CP_COMMIT() asm volatile("cp.async.commit_group;" ::: "memory")
template<int N>
__device__ __forceinline__ void cp_wait() {
    asm volatile("cp.async.wait_group %0;" :: "n"(N) : "memory");
}

__device__ __forceinline__ void ldsm4(uint32_t* r, uint32_t addr) {
    asm volatile("ldmatrix.sync.aligned.m8n8.x4.shared.b16 {%0,%1,%2,%3}, [%4];"
        : "=r"(r[0]), "=r"(r[1]), "=r"(r[2]), "=r"(r[3]) : "r"(addr));
}
// c += a*b, f32 accumulator (in-place)
__device__ __forceinline__ void mma16816(float* c, const uint32_t* a, uint32_t b0, uint32_t b1) {
    asm volatile("mma.sync.aligned.m16n8k16.row.col.f32.f16.f16.f32 "
        "{%0,%1,%2,%3},{%4,%5,%6,%7},{%8,%9},{%0,%1,%2,%3};"
        : "+f"(c[0]), "+f"(c[1]), "+f"(c[2]), "+f"(c[3])
        : "r"(a[0]), "r"(a[1]), "r"(a[2]), "r"(a[3]), "r"(b0), "r"(b1));
}
// d = a*b + 0, f32 accum (fresh fragment)
__device__ __forceinline__ void mma16816_z(float* d, const uint32_t* a, uint32_t b0, uint32_t b1) {
    asm volatile("mma.sync.aligned.m16n8k16.row.col.f32.f16.f16.f32 "
        "{%0,%1,%2,%3},{%4,%5,%6,%7},{%8,%9},{%10,%10,%10,%10};"
        : "=f"(d[0]), "=f"(d[1]), "=f"(d[2]), "=f"(d[3])
        : "r"(a[0]), "r"(a[1]), "r"(a[2]), "r"(a[3]), "r"(b0), "r"(b1), "f"(0.0f));
}
// c += a*b, f16 accumulator (2 b32 regs hold 4 halves)
__device__ __forceinline__ void mma16816_h(uint32_t* c, const uint32_t* a, uint32_t b0, uint32_t b1) {
    asm volatile("mma.sync.aligned.m16n8k16.row.col.f16.f16.f16.f16 "
        "{%0,%1},{%2,%3,%4,%5},{%6,%7},{%0,%1};"
        : "+r"(c[0]), "+r"(c[1])
        : "r"(a[0]), "r"(a[1]), "r"(a[2]), "r"(a[3]), "r"(b0), "r"(b1));
}
#define SWZ(o) ((o) ^ (((o) >> 3) & 0x70))

__device__ __forceinline__ float q8(float v) { return rintf(v * 256.0f) * 0.00390625f; }

__device__ __forceinline__ float gelu_pwl(float v, const float* Ys) {
    if (v > 4.0f) return v;
    if (v < -4.0f) return 0.0f;
    float u = (v + 4.0f) * 4.0f;      // exact on q8 grid
    int idx = (int)u; if (idx > 31) idx = 31;
    float f = u - (float)idx;
    float y0 = Ys[idx], y1 = Ys[idx + 1];
    return fmaf(f, y1 - y0, y0);
}

// ---------------- prepass ----------------
__device__ __forceinline__ void split1(float x, __half& h, __half& l) {
    h = __float2half_rn(x);
    l = __float2half_rn((x - __half2float(h)) * 2048.0f);
}
__global__ void split_x_kernel(const float4* __restrict__ in, __half* __restrict__ hi,
                               __half* __restrict__ lo, int n4) {
    int i = blockIdx.x * blockDim.x + threadIdx.x;
    if (i >= n4) return;
    float4 v = in[i];
    __half h[4], l[4];
    split1(v.x, h[0], l[0]); split1(v.y, h[1], l[1]);
    split1(v.z, h[2], l[2]); split1(v.w, h[3], l[3]);
    *(uint2*)(hi + (size_t)i * 4) = *(uint2*)h;
    *(uint2*)(lo + (size_t)i * 4) = *(uint2*)l;
}
// in: [R, C] f32 -> hi/lo: [C, R] fp16 (transpose + split)
__global__ void transpose_split_kernel(const float* __restrict__ in, __half* __restrict__ hi,
                                       __half* __restrict__ lo, int R, int C) {
    __shared__ float t[32][33];
    int c0 = blockIdx.x * 32, r0 = blockIdx.y * 32;
    int tx = threadIdx.x, ty = threadIdx.y;   // 32 x 8
    #pragma unroll
    for (int i = 0; i < 32; i += 8)
        t[ty + i][tx] = in[(size_t)(r0 + ty + i) * C + c0 + tx];
    __syncthreads();
    #pragma unroll
    for (int i = 0; i < 32; i += 8) {
        __half h, l; split1(t[tx][ty + i], h, l);
        size_t o = (size_t)(c0 + ty + i) * R + r0 + tx;
        hi[o] = h; lo[o] = l;
    }
}

// ---------------- main GEMM ----------------
// C[M,N] = A[M,K] @ B[N,K]^T (+bias, q8, optional PWL-GELU)
// 8 warps, 4x2 grid, warp tile 32x64.
// MAIN_FLUSH=false: main term = plain f32 MMA chain (GEMM1).
// MAIN_FLUSH=true:  main term = chain-2 z-MMA + RN FADD flush (GEMM2).
template<bool HAS_ALO, bool GELU, bool MAIN_FLUSH, int NST>
__global__ void __launch_bounds__(NTHREADS, 1)
gemm_mma(const __half* __restrict__ A, const __half* __restrict__ Alo,
         const __half* __restrict__ B, const __half* __restrict__ Blo,
         const float* __restrict__ bias,
         __half* __restrict__ outH, float* __restrict__ outF,
         int K, int N)
{
    constexpr int OFF_ALO = 16384;
    constexpr int OFF_BHI = HAS_ALO ? 32768 : 16384;
    constexpr int OFF_BLO = OFF_BHI + 16384;
    constexpr int SBYTES  = HAS_ALO ? 65536 : 49152;
    constexpr int PD      = NST - 1;     // prefetch distance

    extern __shared__ char smem[];
    const uint32_t sb = smem_u32(smem);
    __shared__ float Ys[33];

    const int tid = threadIdx.x;
    const int wid = tid >> 5, l = tid & 31;
    const int mTile = blockIdx.y * BM, nTile = blockIdx.x * BN;
    const int warpM = wid & 3, warpN = wid >> 2;   // 4x2 warp grid
    const int m0 = warpM * 32, n0 = warpN * 64;
    const int nK = K / BK;

    if (GELU && tid < 33) Ys[tid] = d_pwl_y[tid];

    // ---- ldmatrix address precompute ----
    const uint32_t rx = (uint32_t)((l & 7) << 4);
    uint32_t kpA[4], kpB[4];
    #pragma unroll
    for (int ks = 0; ks < 4; ks++) {
        kpA[ks] = ((uint32_t)(ks * 32 + ((l >> 4) << 4))) ^ rx;
        kpB[ks] = ((uint32_t)(ks * 32 + (((l >> 3) & 1) << 4))) ^ rx;
    }
    uint32_t aoff[2], boff[4];
    #pragma unroll
    for (int mt = 0; mt < 2; mt++) aoff[mt] = (uint32_t)((m0 + mt * 16 + (l & 15)) * 128);
    #pragma unroll
    for (int p = 0; p < 4; p++)
        boff[p] = (uint32_t)((n0 + p * 16 + ((l >> 4) << 3) + (l & 7)) * 128);

    float    accm[2][8][4];   // main f32
    uint32_t accx[2][8][2];   // cross (x2048) in f16 accumulators
    #pragma unroll
    for (int mt = 0; mt < 2; mt++)
        #pragma unroll
        for (int t = 0; t < 8; t++) {
            #pragma unroll
            for (int j = 0; j < 4; j++) accm[mt][t][j] = 0.0f;
            accx[mt][t][0] = 0u; accx[mt][t][1] = 0u;
        }

    // ---- stage loader (256 threads: 4 chunks of 16B per 16KB tile) ----
    auto load_stage = [&](int kt, int s) {
        const uint32_t sbase = sb + s * SBYTES;
        const int k0 = kt * BK;
        #pragma unroll
        for (int i = 0; i < 4; i++) {
            int c = tid + i * NTHREADS;
            int r = c >> 3, cc = c & 7;
            uint32_t so = SWZ((uint32_t)(r * 128 + cc * 16));
            const __half* gA = A + (size_t)(mTile + r) * K + k0 + cc * 8;
            CP16(sbase + so, gA);
            if (HAS_ALO) {
                const __half* gAl = Alo + (size_t)(mTile + r) * K + k0 + cc * 8;
                CP16(sbase + OFF_ALO + so, gAl);
            }
            const __half* gB  = B   + (size_t)(nTile + r) * K + k0 + cc * 8;
            const __half* gBl = Blo + (size_t)(nTile + r) * K + k0 + cc * 8;
            CP16(sbase + OFF_BHI + so, gB);
            CP16(sbase + OFF_BLO + so, gBl);
        }
    };

    #pragma unroll
    for (int i = 0; i < PD; i++) { load_stage(i, i); CP_COMMIT(); }

    for (int kt = 0; kt < nK; kt++) {
        cp_wait<PD - 1>();
        __syncthreads();
        const int s = kt % NST;
        if (kt + PD < nK) load_stage(kt + PD, (kt + PD) % NST);
        CP_COMMIT();

        const uint32_t st = sb + s * SBYTES;

        if (!MAIN_FLUSH) {
            // ---- GEMM1 path: plain chained main + f16 cross ----
            #pragma unroll
            for (int ks = 0; ks < 4; ks++) {
                uint32_t ah[2][4], al[2][4];
                #pragma unroll
                for (int mt = 0; mt < 2; mt++) {
                    ldsm4(ah[mt], st + aoff[mt] + kpA[ks]);
                    if (HAS_ALO) ldsm4(al[mt], st + OFF_ALO + aoff[mt] + kpA[ks]);
                }
                #pragma unroll
                for (int p = 0; p < 4; p++) {
                    uint32_t bh[4], bl[4];
                    ldsm4(bh, st + OFF_BHI + boff[p] + kpB[ks]);
                    ldsm4(bl, st + OFF_BLO + boff[p] + kpB[ks]);
                    #pragma unroll
                    for (int tt = 0; tt < 2; tt++) {
                        const int t = p * 2 + tt;
                        const uint32_t h0 = bh[tt * 2], h1 = bh[tt * 2 + 1];
                        const uint32_t l0 = bl[tt * 2], l1 = bl[tt * 2 + 1];
                        #pragma unroll
                        for (int mt = 0; mt < 2; mt++) {
                            mma16816(accm[mt][t], ah[mt], h0, h1);
                            mma16816_h(accx[mt][t], ah[mt], l0, l1);
                            if (HAS_ALO) mma16816_h(accx[mt][t], al[mt], h0, h1);
                        }
                    }
                }
            }
        } else {
            // ---- GEMM2 path: chain-2 z-flush main + f16 cross ----
            #pragma unroll
            for (int ks2 = 0; ks2 < 2; ks2++) {
                uint32_t ah[2][2][4];
                #pragma unroll
                for (int mt = 0; mt < 2; mt++)
                    #pragma unroll
                    for (int ksl = 0; ksl < 2; ksl++)
                        ldsm4(ah[mt][ksl], st + aoff[mt] + kpA[ks2 * 2 + ksl]);
                #pragma unroll
                for (int p = 0; p < 4; p++) {
                    uint32_t bh[2][4], bl[2][4];
                    #pragma unroll
                    for (int ksl = 0; ksl < 2; ksl++) {
                        const int ks = ks2 * 2 + ksl;
                        ldsm4(bh[ksl], st + OFF_BHI + boff[p] + kpB[ks]);
                        ldsm4(bl[ksl], st + OFF_BLO + boff[p] + kpB[ks]);
                    }
                    #pragma unroll
                    for (int tt = 0; tt < 2; tt++) {
                        const int t = p * 2 + tt;
                        #pragma unroll
                        for (int mt = 0; mt < 2; mt++) {
                            float tacc[4];
                            mma16816_z(tacc, ah[mt][0], bh[0][tt * 2], bh[0][tt * 2 + 1]);
                            mma16816  (tacc, ah[mt][1], bh[1][tt * 2], bh[1][tt * 2 + 1]);
                            accm[mt][t][0] += tacc[0];
                            accm[mt][t][1] += tacc[1];
                            accm[mt][t][2] += tacc[2];
                            accm[mt][t][3] += tacc[3];
                            mma16816_h(accx[mt][t], ah[mt][0], bl[0][tt * 2], bl[0][tt * 2 + 1]);
                            mma16816_h(accx[mt][t], ah[mt][1], bl[1][tt * 2], bl[1][tt * 2 + 1]);
                        }
                    }
                }
            }
        }
    }

    // ---- epilogue: v = main + cross_f16/2048 + bias ----
    const float invS = 4.8828125e-4f;   // 1/2048
    const int rg = mTile + m0 + (l >> 2);
    const int cg = nTile + n0 + (l & 3) * 2;
    #pragma unroll
    for (int mt = 0; mt < 2; mt++) {
        const int r0r = rg + mt * 16;
        #pragma unroll
        for (int t = 0; t < 8; t++) {
            const int col = cg + t * 8;
            const float b0 = __ldg(bias + col), b1 = __ldg(bias + col + 1);
            const __half2 c01 = *(const __half2*)&accx[mt][t][0];
            const __half2 c23 = *(const __half2*)&accx[mt][t][1];
            float v0 = fmaf(__half2float(__low2half(c01)),  invS, accm[mt][t][0]) + b0;
            float v1 = fmaf(__half2float(__high2half(c01)), invS, accm[mt][t][1]) + b1;
            float v2 = fmaf(__half2float(__low2half(c23)),  invS, accm[mt][t][2]) + b0;
            float v3 = fmaf(__half2float(__high2half(c23)), invS, accm[mt][t][3]) + b1;
            if (GELU) {
                v0 = q8(gelu_pwl(q8(v0), Ys)); v1 = q8(gelu_pwl(q8(v1), Ys));
                v2 = q8(gelu_pwl(q8(v2), Ys)); v3 = q8(gelu_pwl(q8(v3), Ys));
                *(__half2*)(outH + (size_t)r0r * N + col) =
                    __halves2half2(__float2half_rn(v0), __float2half_rn(v1));
                *(__half2*)(outH + (size_t)(r0r + 8) * N + col) =
                    __halves2half2(__float2half_rn(v2), __float2half_rn(v3));
            } else {
                float2 o0 = {q8(v0), q8(v1)}, o1 = {q8(v2), q8(v3)};
                *(float2*)(outF + (size_t)r0r * N + col) = o0;
                *(float2*)(outF + (size_t)(r0r + 8) * N + col) = o1;
            }
        }
    }
}

extern "C" void kernel_launch(void* const* d_in, const int* in_sizes, int n_in,
                              void* d_out, int out_size)
{
    const float* x  = (const float*)d_in[0];
    const float* w1 = (const float*)d_in[1];
    const float* b1 = (const float*)d_in[2];
    const float* w2 = (const float*)d_in[3];
    const float* b2 = (const float*)d_in[4];
    float* out = (float*)d_out;

    __half *a1hi, *a1lo, *w1thi, *w1tlo, *hbuf, *w2thi, *w2tlo;
    cudaGetSymbolAddress((void**)&a1hi, g_a1hi);
    cudaGetSymbolAddress((void**)&a1lo, g_a1lo);
    cudaGetSymbolAddress((void**)&w1thi, g_w1thi);
    cudaGetSymbolAddress((void**)&w1tlo, g_w1tlo);
    cudaGetSymbolAddress((void**)&hbuf, g_hbuf);
    cudaGetSymbolAddress((void**)&w2thi, g_w2thi);
    cudaGetSymbolAddress((void**)&w2tlo, g_w2tlo);

    int n4 = M_ROWS * D_DIM / 4;
    split_x_kernel<<<(n4 + 255) / 256, 256>>>((const float4*)x, a1hi, a1lo, n4);
    transpose_split_kernel<<<dim3(F_DIM / 32, D_DIM / 32), dim3(32, 8)>>>(w1, w1thi, w1tlo, D_DIM, F_DIM);
    transpose_split_kernel<<<dim3(D_DIM / 32, F_DIM / 32), dim3(32, 8)>>>(w2, w2thi, w2tlo, F_DIM, D_DIM);

    constexpr int SMEM1 = 3 * 65536;       // 192 KB
    constexpr int SMEM2 = 3 * 49152;       // 144 KB
    cudaFuncSetAttribute((const void*)gemm_mma<true,  true,  false, 3>,
                         cudaFuncAttributeMaxDynamicSharedMemorySize, SMEM1);
    cudaFuncSetAttribute((const void*)gemm_mma<false, false, true,  3>,
                         cudaFuncAttributeMaxDynamicSharedMemorySize, SMEM2);

    // GEMM1: [16384,1024] x [4096,1024]^T -> h (gelu+q8, fp16); plain main chain
    gemm_mma<true, true, false, 3><<<dim3(F_DIM / BN, M_ROWS / BM), NTHREADS, SMEM1>>>(
        a1hi, a1lo, w1thi, w1tlo, b1, hbuf, nullptr, D_DIM, F_DIM);
    // GEMM2: [16384,4096] x [1024,4096]^T -> out (q8, f32); pair-flushed main
    gemm_mma<false, false, true, 3><<<dim3(D_DIM / BN, M_ROWS / BM), NTHREADS, SMEM2>>>(
        hbuf, hbuf, w2thi, w2tlo, b2, nullptr, out, F_DIM, D_DIM);
}